// round 1
// baseline (speedup 1.0000x reference)
#include <cuda_runtime.h>
#include <math.h>

#define NN 50000
#define NE 600000
#define DD 128

// ---------------- device scratch (static allocation: allowed) ----------------
__device__ int   g_is64;
__device__ int   g_counts[NN];
__device__ int   g_offsets[NN];
__device__ int   g_cursor[NN];
__device__ int   g_srcs[NE];
__device__ float g_agg[(size_t)NN * DD];   // 25.6 MB

// ---------------- dtype detection for edge_index ----------------
// int64 little-endian values < 2^31 => every odd int32 word is 0.
__global__ void k_detect(const void* ei) {
    const int* p = (const int*)ei;
    int all0 = 1;
    for (int i = 1; i < 256; i += 2)
        if (p[i] != 0) all0 = 0;
    g_is64 = all0;
}

__device__ __forceinline__ int ld_idx(const void* ei, int pos, int is64) {
    return is64 ? (int)((const long long*)ei)[pos] : ((const int*)ei)[pos];
}

// ---------------- CSR build ----------------
__global__ void k_zero() {
    int i = blockIdx.x * blockDim.x + threadIdx.x;
    if (i < NN) g_counts[i] = 0;
}

__global__ void k_hist(const void* ei) {
    int e = blockIdx.x * blockDim.x + threadIdx.x;
    if (e < NE) {
        int is64 = g_is64;
        int dst = ld_idx(ei, NE + e, is64);
        atomicAdd(&g_counts[dst], 1);
    }
}

// single-block exclusive scan over 50000 counts
__global__ void k_scan() {
    __shared__ int sums[1024];
    const int T = 1024;
    const int C = (NN + T - 1) / T;  // 49
    int t = threadIdx.x;
    int base = t * C;
    int s = 0;
    for (int i = 0; i < C; i++) {
        int idx = base + i;
        if (idx < NN) s += g_counts[idx];
    }
    sums[t] = s;
    __syncthreads();
    for (int off = 1; off < T; off <<= 1) {
        int v = 0;
        if (t >= off) v = sums[t - off];
        __syncthreads();
        if (t >= off) sums[t] += v;
        __syncthreads();
    }
    int excl = (t == 0) ? 0 : sums[t - 1];
    for (int i = 0; i < C; i++) {
        int idx = base + i;
        if (idx < NN) {
            int c = g_counts[idx];
            g_offsets[idx] = excl;
            g_cursor[idx]  = excl;
            excl += c;
        }
    }
}

__global__ void k_scatter(const void* ei) {
    int e = blockIdx.x * blockDim.x + threadIdx.x;
    if (e < NE) {
        int is64 = g_is64;
        int src = ld_idx(ei, e, is64);
        int dst = ld_idx(ei, NE + e, is64);
        int p = atomicAdd(&g_cursor[dst], 1);
        g_srcs[p] = src;
    }
}

// ---------------- mean aggregation: one warp per node ----------------
__global__ void k_agg(const float* __restrict__ x) {
    int gw   = (blockIdx.x * blockDim.x + threadIdx.x) >> 5;
    int lane = threadIdx.x & 31;
    if (gw >= NN) return;
    int start = g_offsets[gw];
    int cnt   = g_counts[gw];
    const float4* xv = (const float4*)x;
    float4 acc = make_float4(0.f, 0.f, 0.f, 0.f);
    int i = 0;
    for (; i + 1 < cnt; i += 2) {
        int s0 = g_srcs[start + i];
        int s1 = g_srcs[start + i + 1];
        float4 v0 = __ldg(&xv[(size_t)s0 * 32 + lane]);
        float4 v1 = __ldg(&xv[(size_t)s1 * 32 + lane]);
        acc.x += v0.x + v1.x; acc.y += v0.y + v1.y;
        acc.z += v0.z + v1.z; acc.w += v0.w + v1.w;
    }
    if (i < cnt) {
        int s0 = g_srcs[start + i];
        float4 v0 = __ldg(&xv[(size_t)s0 * 32 + lane]);
        acc.x += v0.x; acc.y += v0.y; acc.z += v0.z; acc.w += v0.w;
    }
    float inv = 1.0f / fmaxf((float)cnt, 1.0f);
    float4 r = make_float4(acc.x * inv, acc.y * inv, acc.z * inv, acc.w * inv);
    ((float4*)g_agg)[(size_t)gw * 32 + lane] = r;
}

// ---------------- fused GEMM: out = [agg|x] @ [Wl.T;Wr.T] + b, ELU ----------
// Tile: 128 rows x 128 cols per CTA, 256 threads, 8x8 per thread.
// acc held as f32x2 pairs over column halves (c, c+64); fma.rn.f32x2 packed FMA.
#define BSTR 66   // float2 row stride of Bs (64 pairs + pad)
#define ASTR 17   // float2 row stride of As (16 k + pad)
#define GEMM_SMEM_BYTES (256 * BSTR * 8 + 128 * ASTR * 8 + 128 * 4)

__global__ void __launch_bounds__(256, 1)
k_gemm(const float* __restrict__ x,
       const float* __restrict__ Wl,
       const float* __restrict__ bl,
       const float* __restrict__ Wr,
       float* __restrict__ out) {
    extern __shared__ float sm[];
    float2* Bs   = (float2*)sm;                         // [256][BSTR] pairs (col q, col q+64)
    float2* As   = (float2*)(sm + 256 * BSTR * 2);      // [128][ASTR] duplicated a-values
    float*  bias = sm + 256 * BSTR * 2 + 128 * ASTR * 2;

    int tid = threadIdx.x;
    int m0  = blockIdx.x * 128;

    // Fill Bs: B'[k][j] = (k<128 ? Wl[j][k] : Wr[j][k-128]); paired (j, j+64).
    {
        int wid = tid >> 5, lane = tid & 31;
        for (int j = wid; j < 128; j += 8) {
            float4 vl = ((const float4*)(Wl + (size_t)j * DD))[lane];
            float4 vr = ((const float4*)(Wr + (size_t)j * DD))[lane];
            int q  = (j < 64) ? j : j - 64;
            int hl = (j < 64) ? 0 : 1;
            int k  = lane * 4;
            ((float*)&Bs[(k + 0) * BSTR + q])[hl] = vl.x;
            ((float*)&Bs[(k + 1) * BSTR + q])[hl] = vl.y;
            ((float*)&Bs[(k + 2) * BSTR + q])[hl] = vl.z;
            ((float*)&Bs[(k + 3) * BSTR + q])[hl] = vl.w;
            ((float*)&Bs[(128 + k + 0) * BSTR + q])[hl] = vr.x;
            ((float*)&Bs[(128 + k + 1) * BSTR + q])[hl] = vr.y;
            ((float*)&Bs[(128 + k + 2) * BSTR + q])[hl] = vr.z;
            ((float*)&Bs[(128 + k + 3) * BSTR + q])[hl] = vr.w;
        }
        if (tid < 128) bias[tid] = bl[tid];
    }

    unsigned long long acc[8][4];
    #pragma unroll
    for (int i = 0; i < 8; i++)
        #pragma unroll
        for (int j = 0; j < 4; j++) acc[i][j] = 0ull;

    int tm0 = (tid >> 4) << 3;   // 0..120
    int c0  = tid & 15;          // column base (cols = c0 + 16*j and +64)

    for (int k0 = 0; k0 < 256; k0 += 16) {
        // stage A chunk: thread -> (m = tid/2, kp = (tid&1)*8), 8 floats each
        int m  = tid >> 1;
        int kp = (tid & 1) * 8;
        const float* srcA = (k0 < 128) ? g_agg : x;
        int kb  = (k0 < 128) ? k0 : k0 - 128;
        int row = m0 + m;
        float4 v0 = make_float4(0.f, 0.f, 0.f, 0.f), v1 = v0;
        if (row < NN) {
            const float4* p = (const float4*)(srcA + (size_t)row * DD + kb + kp);
            v0 = p[0]; v1 = p[1];
        }
        __syncthreads();
        As[m * ASTR + kp + 0] = make_float2(v0.x, v0.x);
        As[m * ASTR + kp + 1] = make_float2(v0.y, v0.y);
        As[m * ASTR + kp + 2] = make_float2(v0.z, v0.z);
        As[m * ASTR + kp + 3] = make_float2(v0.w, v0.w);
        As[m * ASTR + kp + 4] = make_float2(v1.x, v1.x);
        As[m * ASTR + kp + 5] = make_float2(v1.y, v1.y);
        As[m * ASTR + kp + 6] = make_float2(v1.z, v1.z);
        As[m * ASTR + kp + 7] = make_float2(v1.w, v1.w);
        __syncthreads();

        #pragma unroll
        for (int kk = 0; kk < 16; kk++) {
            unsigned long long a2[8], b2[4];
            #pragma unroll
            for (int i = 0; i < 8; i++)
                a2[i] = *(const unsigned long long*)&As[(tm0 + i) * ASTR + kk];
            #pragma unroll
            for (int j = 0; j < 4; j++)
                b2[j] = *(const unsigned long long*)&Bs[(k0 + kk) * BSTR + c0 + 16 * j];
            #pragma unroll
            for (int i = 0; i < 8; i++)
                #pragma unroll
                for (int j = 0; j < 4; j++)
                    asm("fma.rn.f32x2 %0, %1, %2, %0;"
                        : "+l"(acc[i][j]) : "l"(a2[i]), "l"(b2[j]));
        }
    }

    // epilogue: bias + ELU
    #pragma unroll
    for (int i = 0; i < 8; i++) {
        int row = m0 + tm0 + i;
        if (row < NN) {
            #pragma unroll
            for (int j = 0; j < 4; j++) {
                float2 v = *(float2*)&acc[i][j];
                int cl = c0 + 16 * j, ch = cl + 64;
                float ol = v.x + bias[cl];
                float oh = v.y + bias[ch];
                ol = (ol > 0.f) ? ol : expm1f(ol);
                oh = (oh > 0.f) ? oh : expm1f(oh);
                out[(size_t)row * DD + cl] = ol;
                out[(size_t)row * DD + ch] = oh;
            }
        }
    }
}

// ---------------- tail: edge_index passthrough (cast to output dtype) -------
__global__ void k_tail(const void* ei, float* out) {
    int i = blockIdx.x * blockDim.x + threadIdx.x;
    if (i < 2 * NE) {
        int is64 = g_is64;
        long long v = is64 ? ((const long long*)ei)[i]
                           : (long long)((const int*)ei)[i];
        out[(size_t)NN * DD + i] = (float)v;
    }
}

// ---------------- launch ----------------
extern "C" void kernel_launch(void* const* d_in, const int* in_sizes, int n_in,
                              void* d_out, int out_size) {
    const float* x  = (const float*)d_in[0];
    const void*  ei = d_in[1];
    const float* Wl = (const float*)d_in[2];
    const float* bl = (const float*)d_in[3];
    const float* Wr = (const float*)d_in[4];
    float* out = (float*)d_out;

    cudaFuncSetAttribute(k_gemm, cudaFuncAttributeMaxDynamicSharedMemorySize,
                         GEMM_SMEM_BYTES);

    k_detect<<<1, 1>>>(ei);
    k_zero<<<(NN + 255) / 256, 256>>>();
    k_hist<<<(NE + 255) / 256, 256>>>(ei);
    k_scan<<<1, 1024>>>();
    k_scatter<<<(NE + 255) / 256, 256>>>(ei);
    k_agg<<<(NN * 32 + 255) / 256, 256>>>(x);
    k_gemm<<<(NN + 127) / 128, 256, GEMM_SMEM_BYTES>>>(x, Wl, bl, Wr, out);
    if (out_size >= NN * DD + 2 * NE)
        k_tail<<<(2 * NE + 255) / 256, 256>>>(ei, out);
}

// round 2
// speedup vs baseline: 1.4003x; 1.4003x over previous
#include <cuda_runtime.h>
#include <math.h>

#define NN 50000
#define NE 600000
#define DD 128

// ---------------- device scratch (static allocation: allowed) ----------------
__device__ int   g_is64;
__device__ int   g_total;
__device__ int   g_counts[NN];
__device__ int   g_offsets[NN];
__device__ int   g_cursor[NN];
__device__ int   g_srcs[NE];
__device__ float g_agg[(size_t)NN * DD];   // 25.6 MB

// ---------------- dtype detection for edge_index ----------------
// int64 little-endian values < 2^31 => every odd int32 word is 0.
__global__ void k_detect(const void* ei) {
    const int* p = (const int*)ei;
    int lane = threadIdx.x;
    // each lane checks 4 odd words (first 128 int64 entries)
    int v = p[lane * 2 + 1] | p[64 + lane * 2 + 1] |
            p[128 + lane * 2 + 1] | p[192 + lane * 2 + 1];
    unsigned any = __ballot_sync(0xffffffffu, v != 0);
    if (lane == 0) g_is64 = (any == 0u);
}

__device__ __forceinline__ int ld_idx(const void* ei, int pos, int is64) {
    return is64 ? (int)((const long long*)ei)[pos] : ((const int*)ei)[pos];
}

// ---------------- CSR build ----------------
__global__ void k_zero() {
    int i = blockIdx.x * blockDim.x + threadIdx.x;
    if (i < NN) g_counts[i] = 0;
    if (i == 0) g_total = 0;
}

__global__ void k_hist(const void* ei) {
    int e = blockIdx.x * blockDim.x + threadIdx.x;
    if (e < NE) {
        int is64 = g_is64;
        int dst = ld_idx(ei, NE + e, is64);
        atomicAdd(&g_counts[dst], 1);
    }
}

// offsets via warp-aggregated atomic bump (bucket order is irrelevant for CSR)
__global__ void k_offsets() {
    int i = blockIdx.x * blockDim.x + threadIdx.x;
    int lane = threadIdx.x & 31;
    int c = (i < NN) ? g_counts[i] : 0;
    int s = c;
    #pragma unroll
    for (int off = 1; off < 32; off <<= 1) {
        int v = __shfl_up_sync(0xffffffffu, s, off);
        if (lane >= off) s += v;
    }
    int total = __shfl_sync(0xffffffffu, s, 31);
    int base = 0;
    if (lane == 31) base = atomicAdd(&g_total, total);
    base = __shfl_sync(0xffffffffu, base, 31);
    int excl = base + s - c;
    if (i < NN) { g_offsets[i] = excl; g_cursor[i] = excl; }
}

__global__ void k_scatter(const void* ei) {
    int e = blockIdx.x * blockDim.x + threadIdx.x;
    if (e < NE) {
        int is64 = g_is64;
        int src = ld_idx(ei, e, is64);
        int dst = ld_idx(ei, NE + e, is64);
        int p = atomicAdd(&g_cursor[dst], 1);
        g_srcs[p] = src;
    }
}

// ---------------- mean aggregation: one warp per node ----------------
__global__ void k_agg(const float* __restrict__ x) {
    int gw   = (blockIdx.x * blockDim.x + threadIdx.x) >> 5;
    int lane = threadIdx.x & 31;
    if (gw >= NN) return;
    int start = g_offsets[gw];
    int cnt   = g_counts[gw];
    const float4* xv = (const float4*)x;
    float4 acc = make_float4(0.f, 0.f, 0.f, 0.f);
    int i = 0;
    for (; i + 1 < cnt; i += 2) {
        int s0 = g_srcs[start + i];
        int s1 = g_srcs[start + i + 1];
        float4 v0 = __ldg(&xv[(size_t)s0 * 32 + lane]);
        float4 v1 = __ldg(&xv[(size_t)s1 * 32 + lane]);
        acc.x += v0.x + v1.x; acc.y += v0.y + v1.y;
        acc.z += v0.z + v1.z; acc.w += v0.w + v1.w;
    }
    if (i < cnt) {
        int s0 = g_srcs[start + i];
        float4 v0 = __ldg(&xv[(size_t)s0 * 32 + lane]);
        acc.x += v0.x; acc.y += v0.y; acc.z += v0.z; acc.w += v0.w;
    }
    float inv = 1.0f / fmaxf((float)cnt, 1.0f);
    float4 r = make_float4(acc.x * inv, acc.y * inv, acc.z * inv, acc.w * inv);
    ((float4*)g_agg)[(size_t)gw * 32 + lane] = r;
}

// ---------------- fused GEMM: out = [agg|x] @ [Wl.T;Wr.T] + b, ELU ----------
// Tile: 128 rows x 128 cols per CTA, 256 threads, 8x8 per thread.
// acc held as f32x2 pairs over column halves (c, c+64); fma.rn.f32x2 packed FMA.
#define BSTR 66   // float2 row stride of Bs (64 pairs + pad)
#define ASTR 17   // float2 row stride of As (16 k + pad)
#define GEMM_SMEM_BYTES (256 * BSTR * 8 + 128 * ASTR * 8 + 128 * 4)

__global__ void __launch_bounds__(256, 1)
k_gemm(const float* __restrict__ x,
       const float* __restrict__ Wl,
       const float* __restrict__ bl,
       const float* __restrict__ Wr,
       float* __restrict__ out) {
    extern __shared__ float sm[];
    float2* Bs   = (float2*)sm;                         // [256][BSTR] pairs (col q, col q+64)
    float2* As   = (float2*)(sm + 256 * BSTR * 2);      // [128][ASTR] duplicated a-values
    float*  bias = sm + 256 * BSTR * 2 + 128 * ASTR * 2;

    int tid = threadIdx.x;
    int m0  = blockIdx.x * 128;

    // Fill Bs: B'[k][j] = (k<128 ? Wl[j][k] : Wr[j][k-128]); paired (j, j+64).
    {
        int wid = tid >> 5, lane = tid & 31;
        for (int j = wid; j < 128; j += 8) {
            float4 vl = ((const float4*)(Wl + (size_t)j * DD))[lane];
            float4 vr = ((const float4*)(Wr + (size_t)j * DD))[lane];
            int q  = (j < 64) ? j : j - 64;
            int hl = (j < 64) ? 0 : 1;
            int k  = lane * 4;
            ((float*)&Bs[(k + 0) * BSTR + q])[hl] = vl.x;
            ((float*)&Bs[(k + 1) * BSTR + q])[hl] = vl.y;
            ((float*)&Bs[(k + 2) * BSTR + q])[hl] = vl.z;
            ((float*)&Bs[(k + 3) * BSTR + q])[hl] = vl.w;
            ((float*)&Bs[(128 + k + 0) * BSTR + q])[hl] = vr.x;
            ((float*)&Bs[(128 + k + 1) * BSTR + q])[hl] = vr.y;
            ((float*)&Bs[(128 + k + 2) * BSTR + q])[hl] = vr.z;
            ((float*)&Bs[(128 + k + 3) * BSTR + q])[hl] = vr.w;
        }
        if (tid < 128) bias[tid] = bl[tid];
    }

    unsigned long long acc[8][4];
    #pragma unroll
    for (int i = 0; i < 8; i++)
        #pragma unroll
        for (int j = 0; j < 4; j++) acc[i][j] = 0ull;

    int tm0 = (tid >> 4) << 3;   // 0..120
    int c0  = tid & 15;          // column base (cols = c0 + 16*j and +64)

    for (int k0 = 0; k0 < 256; k0 += 16) {
        // stage A chunk: thread -> (m = tid/2, kp = (tid&1)*8), 8 floats each
        int m  = tid >> 1;
        int kp = (tid & 1) * 8;
        const float* srcA = (k0 < 128) ? g_agg : x;
        int kb  = (k0 < 128) ? k0 : k0 - 128;
        int row = m0 + m;
        float4 v0 = make_float4(0.f, 0.f, 0.f, 0.f), v1 = v0;
        if (row < NN) {
            const float4* p = (const float4*)(srcA + (size_t)row * DD + kb + kp);
            v0 = p[0]; v1 = p[1];
        }
        __syncthreads();
        As[m * ASTR + kp + 0] = make_float2(v0.x, v0.x);
        As[m * ASTR + kp + 1] = make_float2(v0.y, v0.y);
        As[m * ASTR + kp + 2] = make_float2(v0.z, v0.z);
        As[m * ASTR + kp + 3] = make_float2(v0.w, v0.w);
        As[m * ASTR + kp + 4] = make_float2(v1.x, v1.x);
        As[m * ASTR + kp + 5] = make_float2(v1.y, v1.y);
        As[m * ASTR + kp + 6] = make_float2(v1.z, v1.z);
        As[m * ASTR + kp + 7] = make_float2(v1.w, v1.w);
        __syncthreads();

        #pragma unroll
        for (int kk = 0; kk < 16; kk++) {
            unsigned long long a2[8], b2[4];
            #pragma unroll
            for (int i = 0; i < 8; i++)
                a2[i] = *(const unsigned long long*)&As[(tm0 + i) * ASTR + kk];
            #pragma unroll
            for (int j = 0; j < 4; j++)
                b2[j] = *(const unsigned long long*)&Bs[(k0 + kk) * BSTR + c0 + 16 * j];
            #pragma unroll
            for (int i = 0; i < 8; i++)
                #pragma unroll
                for (int j = 0; j < 4; j++)
                    asm("fma.rn.f32x2 %0, %1, %2, %0;"
                        : "+l"(acc[i][j]) : "l"(a2[i]), "l"(b2[j]));
        }
    }

    // epilogue: bias + ELU
    #pragma unroll
    for (int i = 0; i < 8; i++) {
        int row = m0 + tm0 + i;
        if (row < NN) {
            #pragma unroll
            for (int j = 0; j < 4; j++) {
                float2 v = *(float2*)&acc[i][j];
                int cl = c0 + 16 * j, ch = cl + 64;
                float ol = v.x + bias[cl];
                float oh = v.y + bias[ch];
                ol = (ol > 0.f) ? ol : expm1f(ol);
                oh = (oh > 0.f) ? oh : expm1f(oh);
                out[(size_t)row * DD + cl] = ol;
                out[(size_t)row * DD + ch] = oh;
            }
        }
    }
}

// ---------------- tail: edge_index passthrough (cast to output dtype) -------
__global__ void k_tail(const void* ei, float* out) {
    int i = blockIdx.x * blockDim.x + threadIdx.x;
    if (i < 2 * NE) {
        int is64 = g_is64;
        long long v = is64 ? ((const long long*)ei)[i]
                           : (long long)((const int*)ei)[i];
        out[(size_t)NN * DD + i] = (float)v;
    }
}

// ---------------- launch ----------------
extern "C" void kernel_launch(void* const* d_in, const int* in_sizes, int n_in,
                              void* d_out, int out_size) {
    const float* x  = (const float*)d_in[0];
    const void*  ei = d_in[1];
    const float* Wl = (const float*)d_in[2];
    const float* bl = (const float*)d_in[3];
    const float* Wr = (const float*)d_in[4];
    float* out = (float*)d_out;

    cudaFuncSetAttribute(k_gemm, cudaFuncAttributeMaxDynamicSharedMemorySize,
                         GEMM_SMEM_BYTES);

    k_detect<<<1, 32>>>(ei);
    k_zero<<<(NN + 255) / 256, 256>>>();
    k_hist<<<(NE + 255) / 256, 256>>>(ei);
    k_offsets<<<(NN + 255) / 256, 256>>>();
    k_scatter<<<(NE + 255) / 256, 256>>>(ei);
    k_agg<<<(NN * 32 + 255) / 256, 256>>>(x);
    k_gemm<<<(NN + 127) / 128, 256, GEMM_SMEM_BYTES>>>(x, Wl, bl, Wr, out);
    if (out_size >= NN * DD + 2 * NE)
        k_tail<<<(2 * NE + 255) / 256, 256>>>(ei, out);
}